// round 2
// baseline (speedup 1.0000x reference)
#include <cuda_runtime.h>

// ============================================================================
// ExtractorMLP fused kernel (fp32, packed f32x2 FFMA, cp.async ring pipeline)
//
// out[e] = W3 . relu( relu( [emb[col_e], emb[row_e]] @ W1 + b1 ) @ W2 + b2 ) + b3
//
// TM=64 edges per CTA, 256 threads. h1 chunked into 4x128 columns; GEMM1 chunk
// -> relu -> smem -> GEMM2 accumulated in registers (packed f32x2).
//
// edge_index dtype is probed at runtime (JAX default x64-disabled makes the
// reference's "int64" arrays int32 on disk; probe handles either).
// ============================================================================

#define TM        64
#define NTHREADS  256
#define HID       128
#define SA_STRIDE 260   // 256 + 4 pad
#define SH_STRIDE 132   // 128 + 4 pad
#define SB_STRIDE 132   // 128 + 4 pad
#define KT        32    // K tile

#define OFF_SH (TM * SA_STRIDE)                    // 16640 floats
#define OFF_SB (OFF_SH + TM * SH_STRIDE)           // 25088 floats
#define SMEM_FLOATS (OFF_SB + 4 * KT * SB_STRIDE)  // 41984 floats
#define SMEM_BYTES (SMEM_FLOATS * 4)               // 167936 bytes

typedef unsigned long long u64;

__device__ __forceinline__ u64 fma2(u64 a, u64 b, u64 c) {
    u64 d;
    asm("fma.rn.f32x2 %0, %1, %2, %3;" : "=l"(d) : "l"(a), "l"(b), "l"(c));
    return d;
}
__device__ __forceinline__ u64 pack2(float x) {
    u64 d;
    asm("mov.b64 %0, {%1, %1};" : "=l"(d) : "f"(x));
    return d;
}
__device__ __forceinline__ void unpack2(u64 v, float& lo, float& hi) {
    asm("mov.b64 {%0, %1}, %2;" : "=f"(lo), "=f"(hi) : "l"(v));
}
__device__ __forceinline__ void cp16(float* s, const float* g) {
    unsigned saddr = (unsigned)__cvta_generic_to_shared(s);
    asm volatile("cp.async.cg.shared.global [%0], [%1], 16;" :: "r"(saddr), "l"(g));
}
__device__ __forceinline__ void cp_commit() { asm volatile("cp.async.commit_group;"); }
__device__ __forceinline__ void cp_wait2()  { asm volatile("cp.async.wait_group 2;"); }

// Stage one KT x 128 weight tile into a smem buffer (all 256 threads, 4x16B each)
__device__ __forceinline__ void stage_tile(float* sbuf, const float* gbase, int ldg, int t) {
#pragma unroll
    for (int i = 0; i < 4; ++i) {
        int id = t + i * NTHREADS;     // 0..1023 float4 slots (32 rows x 32 f4)
        int r  = id >> 5;              // 0..31 (k within tile)
        int c4 = (id & 31) << 2;       // 0..124 (col, step 4)
        cp16(sbuf + r * SB_STRIDE + c4, gbase + r * ldg + c4);
    }
    cp_commit();
}

// acc[r][p] : rows m = tr + 16*r, column pairs (8*tc + 2p, 8*tc + 2p + 1)
__device__ __forceinline__ void mma_tile(u64 acc[4][4],
                                         const float* __restrict__ a0p, int row_stride,
                                         const float* __restrict__ bbase) {
#pragma unroll
    for (int k4 = 0; k4 < KT / 4; ++k4) {
        float4 av[4];
#pragma unroll
        for (int r = 0; r < 4; ++r)
            av[r] = *(const float4*)(a0p + r * row_stride + k4 * 4);
        float ar[4][4];
#pragma unroll
        for (int r = 0; r < 4; ++r) {
            ar[r][0] = av[r].x; ar[r][1] = av[r].y; ar[r][2] = av[r].z; ar[r][3] = av[r].w;
        }
#pragma unroll
        for (int j = 0; j < 4; ++j) {
            const float* bj = bbase + (k4 * 4 + j) * SB_STRIDE;
            ulonglong2 b01 = *(const ulonglong2*)(bj);
            ulonglong2 b23 = *(const ulonglong2*)(bj + 4);
#pragma unroll
            for (int r = 0; r < 4; ++r) {
                u64 ad = pack2(ar[r][j]);
                acc[r][0] = fma2(ad, b01.x, acc[r][0]);
                acc[r][1] = fma2(ad, b01.y, acc[r][1]);
                acc[r][2] = fma2(ad, b23.x, acc[r][2]);
                acc[r][3] = fma2(ad, b23.y, acc[r][3]);
            }
        }
    }
}

// K-pipelined GEMM over NT tiles of KT. Ring-4 buffers, distance-2 prefetch,
// one __syncthreads per tile. Safe: a buffer is overwritten only two synced
// iterations after its last read.
template <int NT>
__device__ __forceinline__ void gemm_pipe(u64 acc[4][4],
                                          const float* a_base, int row_stride,
                                          const float* gw, int ldg,
                                          float* sB, int t, int tc) {
    stage_tile(sB, gw, ldg, t);
    stage_tile(sB + KT * SB_STRIDE, gw + KT * ldg, ldg, t);
#pragma unroll 1
    for (int kt = 0; kt < NT; ++kt) {
        if (kt + 2 < NT)
            stage_tile(sB + ((kt + 2) & 3) * KT * SB_STRIDE, gw + (kt + 2) * KT * ldg, ldg, t);
        else
            cp_commit();   // keep group accounting uniform
        cp_wait2();
        __syncthreads();
        mma_tile(acc, a_base + kt * KT, row_stride,
                 sB + (kt & 3) * KT * SB_STRIDE + 8 * tc);
    }
}

__global__ void __launch_bounds__(NTHREADS, 1)
mlp_kernel(const float* __restrict__ emb, const void* __restrict__ ei_raw,
           const float* __restrict__ W1, const float* __restrict__ b1,
           const float* __restrict__ W2, const float* __restrict__ b2,
           const float* __restrict__ W3, const float* __restrict__ b3,
           float* __restrict__ out, int E, int n_nodes) {
    extern __shared__ float smem[];
    float* sA = smem;            // f12, [TM][SA_STRIDE], row-major (m, k)
    float* sH = smem + OFF_SH;   // h1 chunk, [TM][SH_STRIDE]
    float* sB = smem + OFF_SB;   // weight tiles, ring of 4 x [KT][SB_STRIDE]
    __shared__ int sIdx[2 * TM];
    __shared__ int sIs64;

    const int t  = threadIdx.x;
    const int tr = t & 15;       // row group: rows m = tr + 16*r
    const int tc = t >> 4;       // col group: cols n = 8*tc .. 8*tc+7
    const int e0 = blockIdx.x * TM;

    // ---- dtype probe: int32 slots [1,3,..,255] exist under both layouts.
    // All zero  => genuine little-endian int64 (indices < 1e4 => high words 0).
    // Any nonzero => data is int32.
    if (t == 0) sIs64 = 1;
    __syncthreads();
    const int* ei32 = (const int*)ei_raw;
    if (t < 2 * TM) {
        if (ei32[2 * t + 1] != 0) sIs64 = 0;   // benign race: all writers store 0
    }
    __syncthreads();

    // node indices: first TM = col (edge_index row 0), next TM = row (row 1)
    if (t < 2 * TM) {
        int m = t & (TM - 1);
        int half = t >> 6;
        long long pos = (long long)half * E + (e0 + m);
        int v;
        if (sIs64) v = (int)((const long long*)ei_raw)[pos];
        else       v = ei32[pos];
        // clamp: any residual index problem becomes rel_err, not a crash
        v = min(max(v, 0), n_nodes - 1);
        sIdx[t] = v;
    }
    __syncthreads();

    // gather f12: thread t owns feature k=t for all 64 edges
    {
        const int k = t;
        const int half = k >> 7;
        const int kk = k & (HID - 1);
        const int* idx = sIdx + half * TM;
#pragma unroll 8
        for (int m = 0; m < TM; ++m) {
            sA[m * SA_STRIDE + k] = __ldg(emb + (long long)idx[m] * HID + kk);
        }
    }
    // first read of sA happens after GEMM1 iter-0 __syncthreads

    u64 acc2[4][4] = {};                         // h2 accumulator (persistent)
    const float* aG1 = sA + tr * SA_STRIDE;
    const float* aG2 = sH + tr * SH_STRIDE;

#pragma unroll 1
    for (int c = 0; c < 4; ++c) {
        u64 acc1[4][4] = {};
        // GEMM1 chunk: [64 x 256] @ W1[:, c*128 : c*128+128]
        gemm_pipe<8>(acc1, aG1, 16 * SA_STRIDE, W1 + c * HID, 4 * HID, sB, t, tc);

        // epilogue: bias + relu -> sH
        const float* b1c = b1 + c * HID;
#pragma unroll
        for (int r = 0; r < 4; ++r) {
            float* dst = sH + (tr + 16 * r) * SH_STRIDE + 8 * tc;
#pragma unroll
            for (int p = 0; p < 4; ++p) {
                float lo, hi; unpack2(acc1[r][p], lo, hi);
                int n = 8 * tc + 2 * p;
                lo = fmaxf(lo + __ldg(b1c + n), 0.f);
                hi = fmaxf(hi + __ldg(b1c + n + 1), 0.f);
                *(float2*)(dst + 2 * p) = make_float2(lo, hi);
            }
        }
        // GEMM2 accumulate: [64 x 128] @ W2[c*128 : c*128+128, :]
        gemm_pipe<4>(acc2, aG2, 16 * SH_STRIDE, W2 + c * HID * HID, HID, sB, t, tc);
    }

    // final: bias + relu + dot with W3, reduce over the 16 col-groups
    float psum[4] = {0.f, 0.f, 0.f, 0.f};
#pragma unroll
    for (int r = 0; r < 4; ++r) {
#pragma unroll
        for (int p = 0; p < 4; ++p) {
            float lo, hi; unpack2(acc2[r][p], lo, hi);
            int n = 8 * tc + 2 * p;
            lo = fmaxf(lo + __ldg(b2 + n), 0.f);
            hi = fmaxf(hi + __ldg(b2 + n + 1), 0.f);
            psum[r] += lo * __ldg(W3 + n) + hi * __ldg(W3 + n + 1);
        }
    }
    float* sRed = sB;  // reuse ring buffer 0 (safe: last GEMM2 reads hit buffer 3)
#pragma unroll
    for (int r = 0; r < 4; ++r)
        sRed[(tr + 16 * r) * 16 + tc] = psum[r];
    __syncthreads();
    if (t < TM) {
        float s = 0.f;
#pragma unroll
        for (int i = 0; i < 16; ++i) s += sRed[t * 16 + i];
        if (e0 + t < E) out[e0 + t] = s + __ldg(b3);
    }
}

extern "C" void kernel_launch(void* const* d_in, const int* in_sizes, int n_in,
                              void* d_out, int out_size) {
    const float* emb = (const float*)d_in[0];
    const void*  ei  = d_in[1];          // edge_index [2, E], int32 or int64 (probed)
    // d_in[2] = batch (unused by reference output)
    const float* W1 = (const float*)d_in[3];
    const float* b1 = (const float*)d_in[4];
    const float* W2 = (const float*)d_in[5];
    const float* b2 = (const float*)d_in[6];
    const float* W3 = (const float*)d_in[7];
    const float* b3 = (const float*)d_in[8];
    float* out = (float*)d_out;

    int E = in_sizes[1] / 2;             // edge_index element count = 2*E
    int n_nodes = in_sizes[0] / HID;
    int blocks = (E + TM - 1) / TM;

    cudaFuncSetAttribute(mlp_kernel, cudaFuncAttributeMaxDynamicSharedMemorySize, SMEM_BYTES);
    mlp_kernel<<<blocks, NTHREADS, SMEM_BYTES>>>(emb, ei, W1, b1, W2, b2, W3, b3,
                                                 out, E, n_nodes);
}

// round 4
// speedup vs baseline: 2.6603x; 2.6603x over previous
#include <cuda_runtime.h>
#include <cuda_bf16.h>
#include <cstdint>

// ============================================================================
// ExtractorMLP via mma.sync bf16 (HMMA, sm_100-safe) with split-bf16 3-pass.
// out[e] = W3 . relu( relu( [emb[col], emb[row]] @ W1 + b1 ) @ W2 + b2 ) + b3
// 64 edges/CTA, 256 thr (8 warps, 2M x 4N). Weights pre-split hi/lo bf16 and
// pre-swizzled into stage blobs (prep kernel); streamed via cp.async ring-3.
// ============================================================================

#define NTHREADS 256
#define HID      128
#define M_CTA    64
#define NSTAGES  24          // 4 chunks x (4 W1 + 2 W2) stages of [64k x 128n]
#define STAGE_BYTES 32768    // hi 16KB + lo 16KB

// ---- dynamic smem layout (bytes) ----
#define IDX_OFF  0           // 128 node indices (int)
#define FLAG_OFF 512
#define A1H_OFF  1024        // [64 m][256 k] bf16, swizzled
#define A1L_OFF  (A1H_OFF + 32768)
#define HH_OFF   (A1L_OFF + 32768)   // [64 m][128 k] bf16
#define HL_OFF   (HH_OFF + 16384)
#define B_OFF    (HL_OFF + 16384)    // ring of 3 x STAGE_BYTES
#define SMEM_TOTAL (B_OFF + 3 * STAGE_BYTES)   // 197632 B

__device__ __align__(128) unsigned short g_wtiles[NSTAGES * 16384];

// ---------------------------------------------------------------- helpers ---
__device__ __forceinline__ uint32_t smem_u32(const void* p) {
    uint32_t a;
    asm("{ .reg .u64 t; cvta.to.shared.u64 t, %1; cvt.u32.u64 %0, t; }"
        : "=r"(a) : "l"(p));
    return a;
}
__device__ __forceinline__ void cp16(uint32_t s, const void* g) {
    asm volatile("cp.async.cg.shared.global [%0], [%1], 16;" :: "r"(s), "l"(g));
}
#define CP_COMMIT() asm volatile("cp.async.commit_group;")
#define CP_WAIT1()  asm volatile("cp.async.wait_group 1;")

__device__ __forceinline__ void ldsm4(uint32_t* r, uint32_t a) {
    asm volatile("ldmatrix.sync.aligned.m8n8.x4.shared.b16 {%0,%1,%2,%3}, [%4];"
                 : "=r"(r[0]), "=r"(r[1]), "=r"(r[2]), "=r"(r[3]) : "r"(a));
}
__device__ __forceinline__ void ldsm4t(uint32_t* r, uint32_t a) {
    asm volatile("ldmatrix.sync.aligned.m8n8.x4.trans.shared.b16 {%0,%1,%2,%3}, [%4];"
                 : "=r"(r[0]), "=r"(r[1]), "=r"(r[2]), "=r"(r[3]) : "r"(a));
}
__device__ __forceinline__ void mma16816(float* c, const uint32_t* a,
                                         uint32_t b0, uint32_t b1) {
    asm volatile(
        "mma.sync.aligned.m16n8k16.row.col.f32.bf16.bf16.f32 "
        "{%0,%1,%2,%3}, {%4,%5,%6,%7}, {%8,%9}, {%0,%1,%2,%3};"
        : "+f"(c[0]), "+f"(c[1]), "+f"(c[2]), "+f"(c[3])
        : "r"(a[0]), "r"(a[1]), "r"(a[2]), "r"(a[3]), "r"(b0), "r"(b1));
}
// split fp32 pair -> packed hi bf16x2 (truncate) + lo bf16x2 (rn of residual)
__device__ __forceinline__ void split2(float v0, float v1, uint32_t& hi, uint32_t& lo) {
    uint32_t x0 = __float_as_uint(v0), x1 = __float_as_uint(v1);
    hi = (x0 >> 16) | (x1 & 0xffff0000u);
    float r0 = v0 - __uint_as_float(x0 & 0xffff0000u);
    float r1 = v1 - __uint_as_float(x1 & 0xffff0000u);
    lo = (uint32_t)__bfloat16_as_ushort(__float2bfloat16(r0)) |
         ((uint32_t)__bfloat16_as_ushort(__float2bfloat16(r1)) << 16);
}

// ------------------------------------------------------------ prep kernel ---
// Write W tiles as exact smem images: [64 k][128 n] bf16, hi plane then lo,
// element (k,n) at k*256 + ((n>>3)^(k&7))*16 + (n&7)*2. Consumption order:
// for c in 0..3: W1 kt=0..3 then W2 kt2=0..1.
__global__ void prep_kernel(const float* __restrict__ W1, const float* __restrict__ W2) {
    int gid = blockIdx.x * blockDim.x + threadIdx.x;
    if (gid >= NSTAGES * 8192) return;
    int s = gid >> 13, i = gid & 8191;
    int k = i >> 7, n = i & 127;
    int c = s / 6, r = s % 6;
    float v;
    if (r < 4) v = W1[(r * 64 + k) * (4 * HID) + c * HID + n];
    else       v = W2[(c * HID + (r - 4) * 64 + k) * HID + n];
    uint32_t bits = __float_as_uint(v);
    unsigned short hi = (unsigned short)(bits >> 16);
    float res = v - __uint_as_float(bits & 0xffff0000u);
    unsigned short lo = __bfloat16_as_ushort(__float2bfloat16(res));
    int off = k * 256 + (((n >> 3) ^ (k & 7)) << 4) + (n & 7) * 2;
    unsigned short* dst = g_wtiles + (size_t)s * 16384;
    dst[off >> 1] = hi;
    dst[8192 + (off >> 1)] = lo;
}

// ------------------------------------------------------------ stage copy ----
__device__ __forceinline__ void stage_cp(uint32_t sb, int s, int t) {
    const char* src = (const char*)g_wtiles + (size_t)s * STAGE_BYTES;
    uint32_t dst = sb + B_OFF + (uint32_t)(s % 3) * STAGE_BYTES;
#pragma unroll
    for (int i = 0; i < 8; ++i) {
        int o = (t + i * NTHREADS) * 16;
        cp16(dst + o, src + o);
    }
}

// --------------------------------------------------------- stage consume ----
// acc[tm][tn][4] += Ahi*Bhi + Alo*Bhi + Ahi*Blo over a [*,64k] x [64k,128n] tile.
// aH/aL: A plane smem base; arb: A row bytes; ck0: first 8-col chunk index.
__device__ __forceinline__ void consume_stage(float (&acc)[2][4][4],
                                              uint32_t aH, uint32_t aL, int arb,
                                              int ck0, uint32_t bBase,
                                              int wm, int wn, int lane) {
    const int rA = wm * 32 + (lane & 15);
    const int lc = lane >> 4;
    const int x7 = lane & 7;
    const uint32_t aH0 = aH + rA * arb, aH1 = aH0 + 16 * arb;
    const uint32_t aL0 = aL + rA * arb, aL1 = aL0 + 16 * arb;
    const uint32_t offB0 = (uint32_t)(((wn * 4 + lc) ^ x7) << 4);
    const uint32_t offB1 = (uint32_t)(((wn * 4 + 2 + lc) ^ x7) << 4);
    const uint32_t rowB0 = bBase + (uint32_t)(lane & 15) * 256;
#pragma unroll
    for (int kk = 0; kk < 4; ++kk) {
        const uint32_t offA = (uint32_t)(((ck0 + kk * 2 + lc) ^ x7) << 4);
        uint32_t ah[2][4], al[2][4], bh[2][4], bl[2][4];
        ldsm4(ah[0], aH0 + offA);
        ldsm4(ah[1], aH1 + offA);
        ldsm4(al[0], aL0 + offA);
        ldsm4(al[1], aL1 + offA);
        const uint32_t rb = rowB0 + kk * 16 * 256;
        ldsm4t(bh[0], rb + offB0);
        ldsm4t(bh[1], rb + offB1);
        ldsm4t(bl[0], rb + 16384 + offB0);
        ldsm4t(bl[1], rb + 16384 + offB1);
#pragma unroll
        for (int tm = 0; tm < 2; ++tm) {
#pragma unroll
            for (int pr = 0; pr < 2; ++pr) {
                mma16816(acc[tm][pr * 2],     ah[tm], bh[pr][0], bh[pr][1]);
                mma16816(acc[tm][pr * 2 + 1], ah[tm], bh[pr][2], bh[pr][3]);
                mma16816(acc[tm][pr * 2],     al[tm], bh[pr][0], bh[pr][1]);
                mma16816(acc[tm][pr * 2 + 1], al[tm], bh[pr][2], bh[pr][3]);
                mma16816(acc[tm][pr * 2],     ah[tm], bl[pr][0], bl[pr][1]);
                mma16816(acc[tm][pr * 2 + 1], ah[tm], bl[pr][2], bl[pr][3]);
            }
        }
    }
}

// ------------------------------------------------------------ main kernel ---
__global__ void __launch_bounds__(NTHREADS, 1)
mlp_hmma_kernel(const float* __restrict__ emb, const void* __restrict__ ei_raw,
                const float* __restrict__ b1, const float* __restrict__ b2,
                const float* __restrict__ W3, const float* __restrict__ b3,
                float* __restrict__ out, int E, int n_nodes) {
    extern __shared__ __align__(1024) char smem[];
    const uint32_t sb = smem_u32(smem);
    const int t = threadIdx.x;
    const int lane = t & 31, warp = t >> 5;
    const int wm = warp & 1, wn = warp >> 1;
    const int e0 = blockIdx.x * M_CTA;

    // ---- edge_index dtype probe (int32 vs int64, as in round 2) ----
    if (t == 0) *(int*)(smem + FLAG_OFF) = 1;
    __syncthreads();
    const int* ei32 = (const int*)ei_raw;
    if (ei32[2 * t + 1] != 0) *(int*)(smem + FLAG_OFF) = 0;   // benign race
    __syncthreads();
    const int is64 = *(int*)(smem + FLAG_OFF);

    // ---- node indices (clamped) ----
    if (t < 2 * M_CTA) {
        int m = t & (M_CTA - 1), half = t >> 6;
        long long e = e0 + m; if (e >= E) e = E - 1;
        long long pos = (long long)half * E + e;
        int v = is64 ? (int)((const long long*)ei_raw)[pos] : ei32[pos];
        v = min(max(v, 0), n_nodes - 1);
        ((int*)(smem + IDX_OFF))[t] = v;
    }
    __syncthreads();

    // prefetch stages 0,1
    stage_cp(sb, 0, t); CP_COMMIT();
    stage_cp(sb, 1, t); CP_COMMIT();

    // ---- gather f12 -> split hi/lo planes (swizzled) ----
    {
        int m = t >> 2, half = (t >> 1) & 1, kq = t & 1;
        int node = ((const int*)(smem + IDX_OFF))[half * M_CTA + m];
        const float4* src = (const float4*)(emb + (size_t)node * HID);
        const int xm = m & 7;
#pragma unroll 4
        for (int k4 = 0; k4 < 16; ++k4) {
            int kg = half * 128 + kq * 64 + k4 * 4;
            float4 v = __ldg(&src[(kg & 127) >> 2]);
            uint32_t hA, lA, hB, lB;
            split2(v.x, v.y, hA, lA);
            split2(v.z, v.w, hB, lB);
            int off = m * 512 + ((((kg >> 3) ^ xm)) << 4) + (kg & 7) * 2;
            *(uint2*)(smem + A1H_OFF + off) = make_uint2(hA, hB);
            *(uint2*)(smem + A1L_OFF + off) = make_uint2(lA, lB);
        }
    }

    float acc2[2][4][4];
#pragma unroll
    for (int a = 0; a < 2; ++a)
#pragma unroll
        for (int b = 0; b < 4; ++b)
#pragma unroll
            for (int d = 0; d < 4; ++d) acc2[a][b][d] = 0.f;

    int s = 0;
#pragma unroll 1
    for (int c = 0; c < 4; ++c) {
        float acc1[2][4][4];
#pragma unroll
        for (int a = 0; a < 2; ++a)
#pragma unroll
            for (int b = 0; b < 4; ++b)
#pragma unroll
                for (int d = 0; d < 4; ++d) acc1[a][b][d] = 0.f;

        // ---- GEMM1: 4 stages over K=256 ----
#pragma unroll 1
        for (int kt = 0; kt < 4; ++kt) {
            CP_WAIT1(); __syncthreads();
            consume_stage(acc1, sb + A1H_OFF, sb + A1L_OFF, 512, kt * 8,
                          sb + B_OFF + (uint32_t)(s % 3) * STAGE_BYTES, wm, wn, lane);
            if (s + 2 < NSTAGES) stage_cp(sb, s + 2, t);
            CP_COMMIT();
            ++s;
        }
        // ---- epilogue: acc1 -> relu(+b1) -> split -> H planes ----
        {
            const float* b1c = b1 + c * HID;
            const int xh = lane >> 2;
#pragma unroll
            for (int tm = 0; tm < 2; ++tm) {
                int r0 = wm * 32 + tm * 16 + (lane >> 2);
#pragma unroll
                for (int tn = 0; tn < 4; ++tn) {
                    int n0 = wn * 32 + tn * 8 + (lane & 3) * 2;
                    float bb0 = __ldg(b1c + n0), bb1 = __ldg(b1c + n0 + 1);
                    float v00 = fmaxf(acc1[tm][tn][0] + bb0, 0.f);
                    float v01 = fmaxf(acc1[tm][tn][1] + bb1, 0.f);
                    float v10 = fmaxf(acc1[tm][tn][2] + bb0, 0.f);
                    float v11 = fmaxf(acc1[tm][tn][3] + bb1, 0.f);
                    uint32_t h0, l0, h1, l1;
                    split2(v00, v01, h0, l0);
                    split2(v10, v11, h1, l1);
                    int off0 = r0 * 256 + ((((n0 >> 3) ^ xh)) << 4) + (n0 & 7) * 2;
                    int off1 = off0 + 8 * 256;
                    *(uint32_t*)(smem + HH_OFF + off0) = h0;
                    *(uint32_t*)(smem + HL_OFF + off0) = l0;
                    *(uint32_t*)(smem + HH_OFF + off1) = h1;
                    *(uint32_t*)(smem + HL_OFF + off1) = l1;
                }
            }
        }
        // ---- GEMM2: 2 stages over this chunk's K=128 ----
#pragma unroll 1
        for (int kt2 = 0; kt2 < 2; ++kt2) {
            CP_WAIT1(); __syncthreads();   // also makes H writes visible
            consume_stage(acc2, sb + HH_OFF, sb + HL_OFF, 256, kt2 * 8,
                          sb + B_OFF + (uint32_t)(s % 3) * STAGE_BYTES, wm, wn, lane);
            if (s + 2 < NSTAGES) stage_cp(sb, s + 2, t);
            CP_COMMIT();
            ++s;
        }
    }

    // ---- readout: relu(acc2 + b2) . W3, smem reduction ----
    float pr[4] = {0.f, 0.f, 0.f, 0.f};
#pragma unroll
    for (int tm = 0; tm < 2; ++tm) {
#pragma unroll
        for (int tn = 0; tn < 4; ++tn) {
            int n0 = wn * 32 + tn * 8 + (lane & 3) * 2;
            float bb0 = __ldg(b2 + n0), bb1 = __ldg(b2 + n0 + 1);
            float w0 = __ldg(W3 + n0), w1 = __ldg(W3 + n0 + 1);
            pr[tm * 2]     += fmaxf(acc2[tm][tn][0] + bb0, 0.f) * w0;
            pr[tm * 2]     += fmaxf(acc2[tm][tn][1] + bb1, 0.f) * w1;
            pr[tm * 2 + 1] += fmaxf(acc2[tm][tn][2] + bb0, 0.f) * w0;
            pr[tm * 2 + 1] += fmaxf(acc2[tm][tn][3] + bb1, 0.f) * w1;
        }
    }
    __syncthreads();                       // ring buffers now reusable
    float* sRed = (float*)(smem + B_OFF);  // [64][16]
#pragma unroll
    for (int tm = 0; tm < 2; ++tm)
#pragma unroll
        for (int h = 0; h < 2; ++h) {
            int row = wm * 32 + tm * 16 + (lane >> 2) + h * 8;
            sRed[row * 16 + wn * 4 + (lane & 3)] = pr[tm * 2 + h];
        }
    __syncthreads();
    if (t < M_CTA) {
        float ssum = 0.f;
#pragma unroll
        for (int i = 0; i < 16; ++i) ssum += sRed[t * 16 + i];
        int e = e0 + t;
        if (e < E) out[e] = ssum + __ldg(b3);
    }
}

// --------------------------------------------------------------- launcher ---
extern "C" void kernel_launch(void* const* d_in, const int* in_sizes, int n_in,
                              void* d_out, int out_size) {
    const float* emb = (const float*)d_in[0];
    const void*  ei  = d_in[1];          // edge_index [2,E], int32 or int64 (probed)
    const float* W1 = (const float*)d_in[3];
    const float* b1 = (const float*)d_in[4];
    const float* W2 = (const float*)d_in[5];
    const float* b2 = (const float*)d_in[6];
    const float* W3 = (const float*)d_in[7];
    const float* b3 = (const float*)d_in[8];
    float* out = (float*)d_out;

    int E = in_sizes[1] / 2;
    int n_nodes = in_sizes[0] / HID;
    int blocks = (E + M_CTA - 1) / M_CTA;

    prep_kernel<<<(NSTAGES * 8192 + 255) / 256, 256>>>(W1, W2);
    cudaFuncSetAttribute(mlp_hmma_kernel,
                         cudaFuncAttributeMaxDynamicSharedMemorySize, SMEM_TOTAL);
    mlp_hmma_kernel<<<blocks, NTHREADS, SMEM_TOTAL>>>(emb, ei, b1, b2, W3, b3,
                                                      out, E, n_nodes);
}